// round 5
// baseline (speedup 1.0000x reference)
#include <cuda_runtime.h>
#include <cstdint>

#define BATCH   4096
#define SEQ     32
#define DIM     256
#define VOCAB   50257
#define NALIVE  100

// Fused grid: every 5th block is a ctx block (4096), rest are fill (16384).
#define NBTOT   20480
#define NZB     16384
#define TOTAL4  51463168   // BATCH*VOCAB/4

// Scratch: compacted nonzero activations per row (empty in practice).
__device__ float g_val[BATCH * NALIVE];
__device__ int   g_idx[BATCH * NALIVE];
__device__ int   g_cnt[BATCH];

__device__ __forceinline__ float warp_sum(float v) {
    #pragma unroll
    for (int off = 16; off > 0; off >>= 1)
        v += __shfl_xor_sync(0xFFFFFFFFu, v, off);
    return v;
}
__device__ __forceinline__ float warp_max(float v) {
    #pragma unroll
    for (int off = 16; off > 0; off >>= 1)
        v = fmaxf(v, __shfl_xor_sync(0xFFFFFFFFu, v, off));
    return v;
}

__global__ __launch_bounds__(256)
void fused_fill_ctx_kernel(const int*   __restrict__ tok,
                           const float* __restrict__ te,
                           const float* __restrict__ pe,
                           const float* __restrict__ q,
                           const float* __restrict__ pos,
                           float*       __restrict__ out) {
    const int bid = blockIdx.x;
    const int tid = threadIdx.x;            // 0..255

    if ((bid % 5) != 0) {
        // ---------------- zero-fill role (16384 blocks) ----------------
        const int zid = bid - (bid / 5 + 1);             // 0..16383
        const float4 z = make_float4(0.f, 0.f, 0.f, 0.f);
        float4* __restrict__ o4 = (float4*)out;
        const long stride = (long)NZB * 256;
        for (long i = (long)zid * 256 + tid; i < (long)TOTAL4; i += stride)
            __stcs(o4 + i, z);
        return;
    }

    // ---------------- ctx role (4096 blocks, b = bid/5) ----------------
    // No embed staging: te fits in L2 (51.5 MB), read it twice from L2.
    const int b = bid / 5;

    __shared__ float s_q[DIM];        // 1 KB
    __shared__ float s_ctx[DIM];      // 1 KB
    __shared__ float s_score[SEQ];
    __shared__ float s_w[SEQ];
    __shared__ float s_act[NALIVE];
    __shared__ int   s_tok[SEQ];

    const int lane = tid & 31;
    const int wid  = tid >> 5;             // 0..7

    s_q[tid] = q[tid];
    if (tid < SEQ) s_tok[tid] = tok[b * SEQ + tid];
    __syncthreads();

    // Phase B: attention scores, reading embeds from L2 on the fly.
    // Warp w handles s = w, w+8, w+16, w+24.
    #pragma unroll
    for (int s = wid; s < SEQ; s += 8) {
        const float* __restrict__ trow = te + (size_t)s_tok[s] * DIM;
        const float* __restrict__ prow = pe + s * DIM;
        float p = 0.f;
        #pragma unroll
        for (int i = 0; i < 8; i++) {
            int d = lane + 32 * i;
            p = fmaf(__ldg(trow + d) + __ldg(prow + d), s_q[d], p);
        }
        p = warp_sum(p);
        if (lane == 0) s_score[s] = p * (1.0f / 16.0f);   // / sqrt(256)
    }
    __syncthreads();

    // Phase C: softmax over S=32 (warp 0, one score per lane)
    if (wid == 0) {
        float sc = s_score[lane];
        float m  = warp_max(sc);
        float e  = expf(sc - m);
        float s  = warp_sum(e);
        s_w[lane] = e / s;
    }
    __syncthreads();

    // Phase D: context[d] = sum_s w[s] * (te[tok[s]][d] + pe[s][d])  (L2-warm)
    {
        const int d = tid;
        float c = 0.f;
        #pragma unroll
        for (int s = 0; s < SEQ; s++) {
            float e = __ldg(te + (size_t)s_tok[s] * DIM + d) + __ldg(pe + s * DIM + d);
            c = fmaf(s_w[s], e, c);
        }
        s_ctx[d] = c;
    }
    __syncthreads();

    // Phase E: RBF distances to 100 positions (warp w handles j = w, w+8, ...)
    for (int j = wid; j < NALIVE; j += 8) {
        float p = 0.f;
        #pragma unroll
        for (int i = 0; i < 8; i++) {
            int d = lane + 32 * i;
            float df = s_ctx[d] - __ldg(pos + j * DIM + d);
            p = fmaf(df, df, p);
        }
        p = warp_sum(p);
        if (lane == 0) s_act[j] = expf(-2.0f * p);   // exp(-d2 / (2*0.5^2))
    }
    __syncthreads();

    // Phase F: normalize + compact nonzeros (warp 0)
    if (wid == 0) {
        float sum = 0.f;
        for (int j = lane; j < NALIVE; j += 32) sum += s_act[j];
        sum = warp_sum(sum);
        const float denom = sum + 1e-8f;

        int cnt = 0;
        #pragma unroll
        for (int base = 0; base < NALIVE; base += 32) {
            int j = base + lane;
            float a = 0.f;
            bool nz = false;
            if (j < NALIVE) {
                a  = s_act[j] / denom;
                nz = (a != 0.0f);
            }
            unsigned m = __ballot_sync(0xFFFFFFFFu, nz);
            int pre = __popc(m & ((1u << lane) - 1u));
            if (nz) {
                g_val[b * NALIVE + cnt + pre] = a;
                g_idx[b * NALIVE + cnt + pre] = j;
            }
            cnt += __popc(m);
        }
        if (lane == 0) g_cnt[b] = cnt;
    }
}

// Sparse fixup: tiny grid; each block scans 64 rows and recomputes logits for
// any row with surviving activations. Empty in practice (~1-2 us).
__global__ __launch_bounds__(256)
void fixup_kernel(const float* __restrict__ W, float* __restrict__ out) {
    __shared__ float s_val[NALIVE];
    __shared__ int   s_idx[NALIVE];
    const int tid = threadIdx.x;

    for (int b = blockIdx.x; b < BATCH; b += 64) {
        const int cnt = g_cnt[b];
        if (cnt == 0) continue;

        if (tid < cnt) {
            s_val[tid] = g_val[b * NALIVE + tid];
            s_idx[tid] = g_idx[b * NALIVE + tid];
        }
        __syncthreads();

        float* __restrict__ orow = out + (size_t)b * VOCAB;
        for (int v = tid; v < VOCAB; v += 256) {
            float acc = 0.f;
            for (int k = 0; k < cnt; k++)
                acc = fmaf(s_val[k], W[(size_t)s_idx[k] * VOCAB + v], acc);
            orow[v] = acc;
        }
        __syncthreads();
    }
}

extern "C" void kernel_launch(void* const* d_in, const int* in_sizes, int n_in,
                              void* d_out, int out_size) {
    const int*   tok = (const int*)  d_in[0];   // [B, S]
    const float* te  = (const float*)d_in[1];   // [V, D]
    const float* pe  = (const float*)d_in[2];   // [S, D]
    const float* q   = (const float*)d_in[3];   // [D]
    const float* pos = (const float*)d_in[4];   // [N, D]
    const float* W   = (const float*)d_in[5];   // [N, V]
    float* out = (float*)d_out;                 // [B, V]

    fused_fill_ctx_kernel<<<NBTOT, 256>>>(tok, te, pe, q, pos, out);
    fixup_kernel<<<64, 256>>>(W, out);
}

// round 6
// speedup vs baseline: 1.0605x; 1.0605x over previous
#include <cuda_runtime.h>
#include <cstdint>

#define BATCH   4096
#define SEQ     32
#define DIM     256
#define VOCAB   50257
#define NALIVE  100

// Fused grid: every 5th block is a ctx block (4096), rest are fill (16384).
#define NBTOT   20480
#define NZB     16384
#define TOTAL4  51463168   // BATCH*VOCAB/4
#define TE_F4   3216448    // VOCAB*DIM/4

// Scratch: compacted nonzero activations per row (empty in practice).
__device__ float g_val[BATCH * NALIVE];
__device__ int   g_idx[BATCH * NALIVE];
__device__ int   g_cnt[BATCH];
__device__ float g_sink;

__device__ __forceinline__ float warp_sum(float v) {
    #pragma unroll
    for (int off = 16; off > 0; off >>= 1)
        v += __shfl_xor_sync(0xFFFFFFFFu, v, off);
    return v;
}
__device__ __forceinline__ float warp_max(float v) {
    #pragma unroll
    for (int off = 16; off > 0; off >>= 1)
        v = fmaxf(v, __shfl_xor_sync(0xFFFFFFFFu, v, off));
    return v;
}

// L2 prewarm: stream te (51.5 MB, fits in 126 MB L2) at full read BW so the
// fused kernel's gathers are L2 hits and DRAM sees a pure write stream.
__global__ __launch_bounds__(256)
void warm_kernel(const float* __restrict__ te) {
    const float4* __restrict__ t4 = (const float4*)te;
    float acc = 0.f;
    const int stride = gridDim.x * 256;
    for (int i = blockIdx.x * 256 + threadIdx.x; i < TE_F4; i += stride) {
        float4 v = t4[i];
        acc += v.x + v.y + v.z + v.w;
    }
    if (acc == 1.2345e38f) g_sink = acc;   // never true; keeps loads alive
}

__global__ __launch_bounds__(256)
void fused_fill_ctx_kernel(const int*   __restrict__ tok,
                           const float* __restrict__ te,
                           const float* __restrict__ pe,
                           const float* __restrict__ q,
                           const float* __restrict__ pos,
                           float*       __restrict__ out) {
    const int bid = blockIdx.x;
    const int tid = threadIdx.x;            // 0..255

    if ((bid % 5) != 0) {
        // ---------------- zero-fill role (16384 blocks) ----------------
        const int zid = bid - (bid / 5 + 1);             // 0..16383
        const float4 z = make_float4(0.f, 0.f, 0.f, 0.f);
        float4* __restrict__ o4 = (float4*)out;
        const long stride = (long)NZB * 256;
        for (long i = (long)zid * 256 + tid; i < (long)TOTAL4; i += stride)
            __stcs(o4 + i, z);
        return;
    }

    // ---------------- ctx role (4096 blocks, b = bid/5) ----------------
    const int b = bid / 5;

    __shared__ float s_q[DIM];        // 1 KB
    __shared__ float s_ctx[DIM];      // 1 KB
    __shared__ float s_score[SEQ];
    __shared__ float s_w[SEQ];
    __shared__ float s_act[NALIVE];
    __shared__ int   s_tok[SEQ];

    const int lane = tid & 31;
    const int wid  = tid >> 5;             // 0..7

    s_q[tid] = q[tid];
    if (tid < SEQ) s_tok[tid] = tok[b * SEQ + tid];
    __syncthreads();

    // Phase B: attention scores, embeds read from (prewarmed) L2.
    #pragma unroll
    for (int s = wid; s < SEQ; s += 8) {
        const float4* __restrict__ trow = (const float4*)(te + (size_t)s_tok[s] * DIM);
        const float4* __restrict__ prow = (const float4*)(pe + s * DIM);
        float p = 0.f;
        #pragma unroll
        for (int i = 0; i < 2; i++) {
            const int d4 = lane + 32 * i;            // float4 index 0..63
            const float4 t4 = __ldg(trow + d4);
            const float4 p4 = __ldg(prow + d4);
            const float4 q4 = *((const float4*)s_q + d4);
            p = fmaf(t4.x + p4.x, q4.x, p);
            p = fmaf(t4.y + p4.y, q4.y, p);
            p = fmaf(t4.z + p4.z, q4.z, p);
            p = fmaf(t4.w + p4.w, q4.w, p);
        }
        p = warp_sum(p);
        if (lane == 0) s_score[s] = p * (1.0f / 16.0f);   // / sqrt(256)
    }
    __syncthreads();

    // Phase C: softmax over S=32 (warp 0, one score per lane)
    if (wid == 0) {
        float sc = s_score[lane];
        float m  = warp_max(sc);
        float e  = expf(sc - m);
        float s  = warp_sum(e);
        s_w[lane] = e / s;
    }
    __syncthreads();

    // Phase D: context[d] = sum_s w[s] * (te[tok[s]][d] + pe[s][d])  (L2-warm)
    {
        const int d = tid;
        float c = 0.f;
        #pragma unroll
        for (int s = 0; s < SEQ; s++) {
            float e = __ldg(te + (size_t)s_tok[s] * DIM + d) + __ldg(pe + s * DIM + d);
            c = fmaf(s_w[s], e, c);
        }
        s_ctx[d] = c;
    }
    __syncthreads();

    // Phase E: RBF distances to 100 positions (warp w handles j = w, w+8, ...)
    for (int j = wid; j < NALIVE; j += 8) {
        float p = 0.f;
        #pragma unroll
        for (int i = 0; i < 8; i++) {
            int d = lane + 32 * i;
            float df = s_ctx[d] - __ldg(pos + j * DIM + d);
            p = fmaf(df, df, p);
        }
        p = warp_sum(p);
        if (lane == 0) s_act[j] = expf(-2.0f * p);   // exp(-d2 / (2*0.5^2))
    }
    __syncthreads();

    // Phase F: normalize + compact nonzeros (warp 0)
    if (wid == 0) {
        float sum = 0.f;
        for (int j = lane; j < NALIVE; j += 32) sum += s_act[j];
        sum = warp_sum(sum);
        const float denom = sum + 1e-8f;

        int cnt = 0;
        #pragma unroll
        for (int base = 0; base < NALIVE; base += 32) {
            int j = base + lane;
            float a = 0.f;
            bool nz = false;
            if (j < NALIVE) {
                a  = s_act[j] / denom;
                nz = (a != 0.0f);
            }
            unsigned m = __ballot_sync(0xFFFFFFFFu, nz);
            int pre = __popc(m & ((1u << lane) - 1u));
            if (nz) {
                g_val[b * NALIVE + cnt + pre] = a;
                g_idx[b * NALIVE + cnt + pre] = j;
            }
            cnt += __popc(m);
        }
        if (lane == 0) g_cnt[b] = cnt;
    }
}

// Sparse fixup: 16 blocks, each checks 256 rows IN PARALLEL (one load round),
// exits immediately when all counts are zero (the common case, ~2 us).
__global__ __launch_bounds__(256)
void fixup_kernel(const float* __restrict__ W, float* __restrict__ out) {
    __shared__ int   s_cnt_arr[256];
    __shared__ float s_val[NALIVE];
    __shared__ int   s_idx[NALIVE];

    const int tid = threadIdx.x;
    const int b0  = blockIdx.x * 256;

    const int mycnt = g_cnt[b0 + tid];
    s_cnt_arr[tid] = mycnt;
    if (__syncthreads_count(mycnt != 0) == 0) return;   // all-zero: exit

    for (int r = 0; r < 256; r++) {
        const int cnt = s_cnt_arr[r];
        if (cnt == 0) continue;
        const int b = b0 + r;

        if (tid < cnt) {
            s_val[tid] = g_val[b * NALIVE + tid];
            s_idx[tid] = g_idx[b * NALIVE + tid];
        }
        __syncthreads();

        float* __restrict__ orow = out + (size_t)b * VOCAB;
        for (int v = tid; v < VOCAB; v += 256) {
            float acc = 0.f;
            for (int k = 0; k < cnt; k++)
                acc = fmaf(s_val[k], W[(size_t)s_idx[k] * VOCAB + v], acc);
            orow[v] = acc;
        }
        __syncthreads();
    }
}

extern "C" void kernel_launch(void* const* d_in, const int* in_sizes, int n_in,
                              void* d_out, int out_size) {
    const int*   tok = (const int*)  d_in[0];   // [B, S]
    const float* te  = (const float*)d_in[1];   // [V, D]
    const float* pe  = (const float*)d_in[2];   // [S, D]
    const float* q   = (const float*)d_in[3];   // [D]
    const float* pos = (const float*)d_in[4];   // [N, D]
    const float* W   = (const float*)d_in[5];   // [N, V]
    float* out = (float*)d_out;                 // [B, V]

    warm_kernel<<<148, 256>>>(te);
    fused_fill_ctx_kernel<<<NBTOT, 256>>>(tok, te, pe, q, pos, out);
    fixup_kernel<<<16, 256>>>(W, out);
}

// round 8
// speedup vs baseline: 1.1547x; 1.0889x over previous
#include <cuda_runtime.h>
#include <cstdint>

#define BATCH   4096
#define SEQ     32
#define DIM     256
#define VOCAB   50257
#define NALIVE  100

// Fused grid: every 4th block is a ctx block (4096), rest are fill (12288).
#define NBTOT   16384
#define NZB     12288
#define TOTAL4  51463168   // BATCH*VOCAB/4

// Scratch: compacted nonzero activations per row (empty in practice).
__device__ float g_val[BATCH * NALIVE];
__device__ int   g_idx[BATCH * NALIVE];
__device__ int   g_cnt[BATCH];

__device__ __forceinline__ float warp_sum(float v) {
    #pragma unroll
    for (int off = 16; off > 0; off >>= 1)
        v += __shfl_xor_sync(0xFFFFFFFFu, v, off);
    return v;
}
__device__ __forceinline__ float warp_max(float v) {
    #pragma unroll
    for (int off = 16; off > 0; off >>= 1)
        v = fmaxf(v, __shfl_xor_sync(0xFFFFFFFFu, v, off));
    return v;
}

// 32-byte gather load with L2 evict_last (sm_103a requires .v4.b64/.v8.b32
// width for this policy). Keeps te resident in L2 against the evict_first
// (__stcs) output write stream.
__device__ __forceinline__ void ldg32_evict_last(const float* p, float4& lo, float4& hi) {
    unsigned long long r0, r1, r2, r3;
    asm volatile("ld.global.nc.L2::evict_last.v4.b64 {%0,%1,%2,%3}, [%4];"
                 : "=l"(r0), "=l"(r1), "=l"(r2), "=l"(r3) : "l"(p));
    lo.x = __uint_as_float((unsigned)(r0));
    lo.y = __uint_as_float((unsigned)(r0 >> 32));
    lo.z = __uint_as_float((unsigned)(r1));
    lo.w = __uint_as_float((unsigned)(r1 >> 32));
    hi.x = __uint_as_float((unsigned)(r2));
    hi.y = __uint_as_float((unsigned)(r2 >> 32));
    hi.z = __uint_as_float((unsigned)(r3));
    hi.w = __uint_as_float((unsigned)(r3 >> 32));
}

__global__ __launch_bounds__(256)
void fused_fill_ctx_kernel(const int*   __restrict__ tok,
                           const float* __restrict__ te,
                           const float* __restrict__ pe,
                           const float* __restrict__ q,
                           const float* __restrict__ pos,
                           float*       __restrict__ out) {
    const int bid = blockIdx.x;
    const int tid = threadIdx.x;            // 0..255

    if ((bid & 3) != 0) {
        // ---------------- zero-fill role (12288 blocks) ----------------
        const int zid = bid - ((bid + 3) >> 2);          // 0..12287
        const float4 z = make_float4(0.f, 0.f, 0.f, 0.f);
        float4* __restrict__ o4 = (float4*)out;
        const long stride = (long)NZB * 256;
        for (long i = (long)zid * 256 + tid; i < (long)TOTAL4; i += stride)
            __stcs(o4 + i, z);
        return;
    }

    // ---------------- ctx role (4096 blocks, b = bid/4) ----------------
    const int b = bid >> 2;

    __shared__ float s_emb[SEQ][DIM];     // 32 KB
    __shared__ float s_q[DIM];
    __shared__ float s_ctx[DIM];
    __shared__ float s_score[SEQ];
    __shared__ float s_w[SEQ];
    __shared__ float s_act[NALIVE];
    __shared__ int   s_tok[SEQ];

    const int lane = tid & 31;
    const int wid  = tid >> 5;             // 0..7

    s_q[tid] = q[tid];
    if (tid < SEQ) s_tok[tid] = tok[b * SEQ + tid];
    __syncthreads();

    // Phase A: gather embeds into smem. One warp per row (32 lanes x 32B = 1KB
    // row), 8 rows per pass, 4 passes. te loads are 256-bit evict_last.
    {
        #pragma unroll
        for (int p = 0; p < 4; p++) {
            const int s = p * 8 + wid;
            float4 tlo, thi;
            ldg32_evict_last(te + (size_t)s_tok[s] * DIM + lane * 8, tlo, thi);
            const float4 plo = __ldg((const float4*)(pe + s * DIM) + lane * 2);
            const float4 phi = __ldg((const float4*)(pe + s * DIM) + lane * 2 + 1);
            float4 e0, e1;
            e0.x = tlo.x + plo.x; e0.y = tlo.y + plo.y;
            e0.z = tlo.z + plo.z; e0.w = tlo.w + plo.w;
            e1.x = thi.x + phi.x; e1.y = thi.y + phi.y;
            e1.z = thi.z + phi.z; e1.w = thi.w + phi.w;
            *((float4*)&s_emb[s][0] + lane * 2)     = e0;
            *((float4*)&s_emb[s][0] + lane * 2 + 1) = e1;
        }
    }
    __syncthreads();

    // Phase B: attention scores (warp w handles s = w, w+8, w+16, w+24)
    #pragma unroll
    for (int s = wid; s < SEQ; s += 8) {
        float p = 0.f;
        #pragma unroll
        for (int i = 0; i < 8; i++) {
            int d = lane + 32 * i;
            p = fmaf(s_emb[s][d], s_q[d], p);
        }
        p = warp_sum(p);
        if (lane == 0) s_score[s] = p * (1.0f / 16.0f);   // / sqrt(256)
    }
    __syncthreads();

    // Phase C: softmax over S=32 (warp 0, one score per lane)
    if (wid == 0) {
        float sc = s_score[lane];
        float m  = warp_max(sc);
        float e  = expf(sc - m);
        float s  = warp_sum(e);
        s_w[lane] = e / s;
    }
    __syncthreads();

    // Phase D: context[d] = sum_s w[s] * embeds[s][d]
    {
        float c = 0.f;
        #pragma unroll
        for (int s = 0; s < SEQ; s++) c = fmaf(s_w[s], s_emb[s][tid], c);
        s_ctx[tid] = c;
    }
    __syncthreads();

    // Phase E: RBF distances to 100 positions (warp w handles j = w, w+8, ...)
    for (int j = wid; j < NALIVE; j += 8) {
        float p = 0.f;
        #pragma unroll
        for (int i = 0; i < 8; i++) {
            int d = lane + 32 * i;
            float df = s_ctx[d] - __ldg(pos + j * DIM + d);
            p = fmaf(df, df, p);
        }
        p = warp_sum(p);
        if (lane == 0) s_act[j] = expf(-2.0f * p);   // exp(-d2 / (2*0.5^2))
    }
    __syncthreads();

    // Phase F: normalize + compact nonzeros (warp 0)
    if (wid == 0) {
        float sum = 0.f;
        for (int j = lane; j < NALIVE; j += 32) sum += s_act[j];
        sum = warp_sum(sum);
        const float denom = sum + 1e-8f;

        int cnt = 0;
        #pragma unroll
        for (int base = 0; base < NALIVE; base += 32) {
            int j = base + lane;
            float a = 0.f;
            bool nz = false;
            if (j < NALIVE) {
                a  = s_act[j] / denom;
                nz = (a != 0.0f);
            }
            unsigned m = __ballot_sync(0xFFFFFFFFu, nz);
            int pre = __popc(m & ((1u << lane) - 1u));
            if (nz) {
                g_val[b * NALIVE + cnt + pre] = a;
                g_idx[b * NALIVE + cnt + pre] = j;
            }
            cnt += __popc(m);
        }
        if (lane == 0) g_cnt[b] = cnt;
    }
}

// Sparse fixup: 16 blocks, each checks 256 rows IN PARALLEL (one load round),
// exits immediately when all counts are zero (the common case, ~2 us).
__global__ __launch_bounds__(256)
void fixup_kernel(const float* __restrict__ W, float* __restrict__ out) {
    __shared__ int   s_cnt_arr[256];
    __shared__ float s_val[NALIVE];
    __shared__ int   s_idx[NALIVE];

    const int tid = threadIdx.x;
    const int b0  = blockIdx.x * 256;

    const int mycnt = g_cnt[b0 + tid];
    s_cnt_arr[tid] = mycnt;
    if (__syncthreads_count(mycnt != 0) == 0) return;   // all-zero: exit

    for (int r = 0; r < 256; r++) {
        const int cnt = s_cnt_arr[r];
        if (cnt == 0) continue;
        const int b = b0 + r;

        if (tid < cnt) {
            s_val[tid] = g_val[b * NALIVE + tid];
            s_idx[tid] = g_idx[b * NALIVE + tid];
        }
        __syncthreads();

        float* __restrict__ orow = out + (size_t)b * VOCAB;
        for (int v = tid; v < VOCAB; v += 256) {
            float acc = 0.f;
            for (int k = 0; k < cnt; k++)
                acc = fmaf(s_val[k], W[(size_t)s_idx[k] * VOCAB + v], acc);
            orow[v] = acc;
        }
        __syncthreads();
    }
}

extern "C" void kernel_launch(void* const* d_in, const int* in_sizes, int n_in,
                              void* d_out, int out_size) {
    const int*   tok = (const int*)  d_in[0];   // [B, S]
    const float* te  = (const float*)d_in[1];   // [V, D]
    const float* pe  = (const float*)d_in[2];   // [S, D]
    const float* q   = (const float*)d_in[3];   // [D]
    const float* pos = (const float*)d_in[4];   // [N, D]
    const float* W   = (const float*)d_in[5];   // [N, V]
    float* out = (float*)d_out;                 // [B, V]

    fused_fill_ctx_kernel<<<NBTOT, 256>>>(tok, te, pe, q, pos, out);
    fixup_kernel<<<16, 256>>>(W, out);
}